// round 4
// baseline (speedup 1.0000x reference)
#include <cuda_runtime.h>

// ---------------------------------------------------------------------------
// GCN 2-layer: h = ReLU(BN(GCNConv(x,W1,b1)));  out = GCNConv(h,W2,b2)
// GCNConv(x)[i] = sum_{e: dst=i} norm_e * (xW)[src_e] + dinv[i]^2 * (xW)[i] + b
// norm_e = dinv[src]*w_e*dinv[dst],  deg[i] = 1 + sum_{e: dst=i} w_e
// NOTE: edge_index arrives as int32 (JAX x64 disabled demotes int64 -> int32).
// ---------------------------------------------------------------------------

#define N_MAX 50000
#define E_MAX 800000
#define D1 128
#define D2 64

__device__ float g_deg [N_MAX];
__device__ float g_dinv[N_MAX];
__device__ float g_norm[E_MAX];
__device__ float g_xw1 [(size_t)N_MAX * D1];
__device__ float g_agg1[(size_t)N_MAX * D1];   // also holds h after BN/ReLU (in place)
__device__ float g_xw2 [(size_t)N_MAX * D2];

// -------------------------------- helpers ---------------------------------

__device__ __forceinline__ void red_add_f4(float* p, float4 v) {
    asm volatile("red.global.add.v4.f32 [%0], {%1,%2,%3,%4};"
                 :: "l"(p), "f"(v.x), "f"(v.y), "f"(v.z), "f"(v.w)
                 : "memory");
}

// ------------------------------ prep kernels -------------------------------

__global__ void k_init_deg(float* deg, int n) {
    int i = blockIdx.x * blockDim.x + threadIdx.x;
    if (i < n) deg[i] = 1.0f;                    // self-loop weight
}

__global__ void k_zero_f4(float4* p, long long n4) {
    long long i = (long long)blockIdx.x * blockDim.x + threadIdx.x;
    if (i < n4) p[i] = make_float4(0.f, 0.f, 0.f, 0.f);
}

__global__ void k_deg_acc(const int* __restrict__ ei,
                          const float* __restrict__ w,
                          float* __restrict__ deg, int e) {
    int i = blockIdx.x * blockDim.x + threadIdx.x;
    if (i >= e) return;
    atomicAdd(&deg[ei[e + i]], w[i]);            // dst-side degree
}

__global__ void k_dinv(const float* __restrict__ deg, float* __restrict__ dinv, int n) {
    int i = blockIdx.x * blockDim.x + threadIdx.x;
    if (i < n) {
        float d = deg[i];
        dinv[i] = d > 0.f ? rsqrtf(d) : 0.f;
    }
}

__global__ void k_norm(const int* __restrict__ ei,
                       const float* __restrict__ w, const float* __restrict__ dinv,
                       float* __restrict__ norm, int e) {
    int i = blockIdx.x * blockDim.x + threadIdx.x;
    if (i < e) norm[i] = dinv[ei[i]] * w[i] * dinv[ei[e + i]];
}

// -------------------------------- GEMM -------------------------------------
// Y[n, COLS] = X[n, 128] @ W[128, COLS].  W cached in (dynamic) shared memory.

template <int COLS>
__global__ void k_gemm(const float* __restrict__ X, const float* __restrict__ W,
                       float* __restrict__ Y, int n) {
    extern __shared__ float Wsh[];               // 128 * COLS floats
    constexpr int ROWS_BLK = 64;
    constexpr int RPI = 256 / COLS;              // rows per iteration
    for (int i = threadIdx.x; i < 128 * COLS; i += 256) Wsh[i] = W[i];
    __syncthreads();

    int col  = threadIdx.x % COLS;
    int rsub = threadIdx.x / COLS;
    int row0 = blockIdx.x * ROWS_BLK;
    int rend = min(row0 + ROWS_BLK, n);

    for (int r = row0 + rsub; r < rend; r += RPI) {
        const float4* xr = (const float4*)(X + (size_t)r * 128);
        float acc = 0.f;
#pragma unroll
        for (int k4 = 0; k4 < 32; k4++) {
            float4 xv = xr[k4];
            acc = fmaf(xv.x, Wsh[(k4 * 4 + 0) * COLS + col], acc);
            acc = fmaf(xv.y, Wsh[(k4 * 4 + 1) * COLS + col], acc);
            acc = fmaf(xv.z, Wsh[(k4 * 4 + 2) * COLS + col], acc);
            acc = fmaf(xv.w, Wsh[(k4 * 4 + 3) * COLS + col], acc);
        }
        Y[(size_t)r * COLS + col] = acc;
    }
}

// ------------------------------ edge scatter -------------------------------
// agg[dst] += norm_e * xw[src]  via 128-bit vector reductions.
// src/dst read straight from the int32 edge_index buffer: ei[0..e) = src,
// ei[e..2e) = dst.

template <int COLS>
__global__ void k_scatter(const float* __restrict__ xw, float* __restrict__ agg,
                          const int* __restrict__ ei,
                          const float* __restrict__ norm, int e) {
    constexpr int VPE = COLS / 4;                // float4 groups per edge
    long long total = (long long)e * VPE;
    long long i = (long long)blockIdx.x * blockDim.x + threadIdx.x;
    if (i >= total) return;
    int eid = (int)(i / VPE);
    int j   = (int)(i % VPE) * 4;
    float nv = norm[eid];
    int s = ei[eid];
    int d = ei[e + eid];
    float4 v = *(const float4*)(xw + (size_t)s * COLS + j);
    v.x *= nv; v.y *= nv; v.z *= nv; v.w *= nv;
    red_add_f4(agg + (size_t)d * COLS + j, v);
}

// ---------------------------- fused epilogues ------------------------------
// Layer 1: h = ReLU(BN(agg1 + dinv^2 * xw1 + b1)); written in place into agg1.

__global__ void k_bnrelu(float* __restrict__ agg, const float* __restrict__ xw,
                         const float* __restrict__ dinv,
                         const float* __restrict__ b1,
                         const float* __restrict__ gamma, const float* __restrict__ beta,
                         const float* __restrict__ rmean, const float* __restrict__ rvar,
                         int n) {
    long long i = (long long)blockIdx.x * blockDim.x + threadIdx.x;   // over n*32 float4s
    if (i >= (long long)n * (D1 / 4)) return;
    int row = (int)(i / (D1 / 4));
    int c4  = (int)(i % (D1 / 4)) * 4;
    float di = dinv[row];
    float sl = di * di;
    float4 a = ((const float4*)agg)[i];
    float4 xv = ((const float4*)xw)[i];
    float4 bb = *(const float4*)(b1 + c4);
    float4 g  = *(const float4*)(gamma + c4);
    float4 be = *(const float4*)(beta + c4);
    float4 m  = *(const float4*)(rmean + c4);
    float4 vv = *(const float4*)(rvar + c4);
    float4 o;
    o.x = fmaxf((a.x + sl * xv.x + bb.x - m.x) * rsqrtf(vv.x + 1e-5f) * g.x + be.x, 0.f);
    o.y = fmaxf((a.y + sl * xv.y + bb.y - m.y) * rsqrtf(vv.y + 1e-5f) * g.y + be.y, 0.f);
    o.z = fmaxf((a.z + sl * xv.z + bb.z - m.z) * rsqrtf(vv.z + 1e-5f) * g.z + be.z, 0.f);
    o.w = fmaxf((a.w + sl * xv.w + bb.w - m.w) * rsqrtf(vv.w + 1e-5f) * g.w + be.w, 0.f);
    ((float4*)agg)[i] = o;
}

// Layer 2 output init: out = dinv^2 * xw2 + b2 (edge scatter then adds on top).

__global__ void k_out_init(float* __restrict__ out, const float* __restrict__ xw,
                           const float* __restrict__ dinv, const float* __restrict__ b2,
                           int n) {
    long long i = (long long)blockIdx.x * blockDim.x + threadIdx.x;   // over n*16 float4s
    if (i >= (long long)n * (D2 / 4)) return;
    int row = (int)(i / (D2 / 4));
    int c4  = (int)(i % (D2 / 4)) * 4;
    float di = dinv[row];
    float sl = di * di;
    float4 xv = ((const float4*)xw)[i];
    float4 bb = *(const float4*)(b2 + c4);
    float4 o;
    o.x = sl * xv.x + bb.x;
    o.y = sl * xv.y + bb.y;
    o.z = sl * xv.z + bb.z;
    o.w = sl * xv.w + bb.w;
    ((float4*)out)[i] = o;
}

// ------------------------------- launcher ----------------------------------

extern "C" void kernel_launch(void* const* d_in, const int* in_sizes, int n_in,
                              void* d_out, int out_size) {
    const float* x     = (const float*)d_in[0];
    const int*   ei    = (const int*)d_in[1];     // int32 [2, E]
    const float* ew    = (const float*)d_in[2];
    const float* W1    = (const float*)d_in[3];
    const float* b1    = (const float*)d_in[4];
    const float* gamma = (const float*)d_in[5];
    const float* beta  = (const float*)d_in[6];
    const float* rmean = (const float*)d_in[7];
    const float* rvar  = (const float*)d_in[8];
    const float* W2    = (const float*)d_in[9];
    const float* b2    = (const float*)d_in[10];
    float* out = (float*)d_out;

    int n = in_sizes[0] / D1;
    int e = in_sizes[2];

    float *deg, *dinv, *norm, *xw1, *agg1, *xw2;
    cudaGetSymbolAddress((void**)&deg,  g_deg);
    cudaGetSymbolAddress((void**)&dinv, g_dinv);
    cudaGetSymbolAddress((void**)&norm, g_norm);
    cudaGetSymbolAddress((void**)&xw1,  g_xw1);
    cudaGetSymbolAddress((void**)&agg1, g_agg1);
    cudaGetSymbolAddress((void**)&xw2,  g_xw2);

    cudaFuncSetAttribute(k_gemm<D1>, cudaFuncAttributeMaxDynamicSharedMemorySize,
                         128 * D1 * (int)sizeof(float));
    cudaFuncSetAttribute(k_gemm<D2>, cudaFuncAttributeMaxDynamicSharedMemorySize,
                         128 * D2 * (int)sizeof(float));

    const int T = 256;
    auto cdiv = [](long long a, long long b) { return (int)((a + b - 1) / b); };

    // --- degree / normalization prep ---
    k_init_deg<<<cdiv(n, T), T>>>(deg, n);
    k_deg_acc<<<cdiv(e, T), T>>>(ei, ew, deg, e);
    k_dinv<<<cdiv(n, T), T>>>(deg, dinv, n);
    k_norm<<<cdiv(e, T), T>>>(ei, ew, dinv, norm, e);

    // --- layer 1 ---
    k_gemm<D1><<<cdiv(n, 64), T, 128 * D1 * sizeof(float)>>>(x, W1, xw1, n);
    k_zero_f4<<<cdiv((long long)n * (D1 / 4), T), T>>>((float4*)agg1, (long long)n * (D1 / 4));
    k_scatter<D1><<<cdiv((long long)e * (D1 / 4), T), T>>>(xw1, agg1, ei, norm, e);
    k_bnrelu<<<cdiv((long long)n * (D1 / 4), T), T>>>(agg1, xw1, dinv, b1, gamma, beta,
                                                      rmean, rvar, n);

    // --- layer 2 ---
    k_gemm<D2><<<cdiv(n, 64), T, 128 * D2 * sizeof(float)>>>(agg1, W2, xw2, n);
    k_out_init<<<cdiv((long long)n * (D2 / 4), T), T>>>(out, xw2, dinv, b2, n);
    k_scatter<D2><<<cdiv((long long)e * (D2 / 4), T), T>>>(xw2, out, ei, norm, e);
}